// round 10
// baseline (speedup 1.0000x reference)
#include <cuda_runtime.h>
#include <cuda_fp16.h>

// PassiveWaveDigitalMixer — fused 9-point periodic stencil + gated flows.
// B=4, C=128, H=W=256, O=16, M=32 (fixed shapes).
// R9: warp = full W row (32 lanes x 8 elems), TWO rows x TWO channels per
// iteration -> 16 front-batched LDG.128 per warp (max MLP at 2 CTA/SM).
// Steer multipliers (channel-invariant) in shared, read via LDS.128 and
// shared by both channels. Packed-half2 gating, fp32 flows, __stcs stores.

constexpr int B = 4, C = 128, H = 256, W = 256, O = 16, M = 32;
constexpr int HW = H * W;
constexpr float GAIN_CAP = 0.99f;
constexpr float EPS = 1e-4f;

__device__ __forceinline__ float softplus_eps(float p) {
    return fmaxf(p, 0.0f) + log1pf(expf(-fabsf(p))) + EPS;
}

__device__ __forceinline__ float4 add4(float4 a, float4 b) {
    return make_float4(a.x + b.x, a.y + b.y, a.z + b.z, a.w + b.w);
}

__device__ __forceinline__ __half2 u2h(unsigned u) {
    __half2 r;
    *reinterpret_cast<unsigned*>(&r) = u;
    return r;
}

__global__ __launch_bounds__(256, 2)
void pwdm_kernel(const float* __restrict__ x,
                 const float* __restrict__ steer,
                 const float* __restrict__ modulation,
                 const float* __restrict__ r_center,
                 const float* __restrict__ r_horizontal,
                 const float* __restrict__ r_vertical,
                 const float* __restrict__ r_diag,
                 const float* __restrict__ gain_h,
                 const float* __restrict__ gain_v,
                 const float* __restrict__ gain_d,
                 const float* __restrict__ steer_w,
                 const float* __restrict__ mod_w,
                 float* __restrict__ out)
{
    __shared__ float s_invh[C], s_invv[C], s_invd[C];
    __shared__ float s_gh[C],   s_gv[C],   s_gd[C];
    __shared__ __half s_t[2][3][W];   // pre-expanded (1 + 0.2*tanh(field))

    const int tx  = threadIdx.x;          // 0..31 lane (8 w-elems each)
    const int ty  = threadIdx.y;          // 0..7  channel-pair sub-lane
    const int tid = ty * 32 + tx;
    const int h0  = blockIdx.x * 2;       // first of the row pair
    const int b   = blockIdx.y;

    // --- modulation deltas (broadcast loads, every thread) ---
    float d0 = 0.f, d1 = 0.f, d2 = 0.f;
    #pragma unroll
    for (int m = 0; m < M; m++) {
        float mv = modulation[b * M + m];
        d0 = fmaf(mv, mod_w[0 * M + m], d0);
        d1 = fmaf(mv, mod_w[1 * M + m], d1);
        d2 = fmaf(mv, mod_w[2 * M + m], d2);
    }
    d0 = tanhf(d0); d1 = tanhf(d1); d2 = tanhf(d2);

    // --- per-channel constants ---
    if (tid < C) {
        float spc = softplus_eps(r_center[tid]);
        s_invh[tid] = 1.0f / (spc + softplus_eps(r_horizontal[tid]));
        s_invv[tid] = 1.0f / (spc + softplus_eps(r_vertical[tid]));
        s_invd[tid] = 1.0f / (2.0f * (spc + softplus_eps(r_diag[tid])));
        s_gh[tid] = tanhf(gain_h[tid]) * (1.0f + 0.1f * d0);
        s_gv[tid] = tanhf(gain_v[tid]) * (1.0f + 0.1f * d1);
        s_gd[tid] = tanhf(gain_d[tid]) * (1.0f + 0.1f * d2);
    }

    // --- steer-field multipliers for the 2 rows; thread tid covers w=tid ---
    #pragma unroll
    for (int r = 0; r < 2; r++) {
        float a0 = 0.f, a1 = 0.f, a2 = 0.f;
        const float* sp = steer + ((size_t)b * O * H + (h0 + r)) * W + tid;
        #pragma unroll
        for (int o = 0; o < O; o++) {
            float v = sp[(size_t)o * HW];
            a0 = fmaf(v, steer_w[0 * O + o], a0);
            a1 = fmaf(v, steer_w[1 * O + o], a1);
            a2 = fmaf(v, steer_w[2 * O + o], a2);
        }
        s_t[r][0][tid] = __float2half(fmaf(0.2f, tanhf(a0), 1.0f));
        s_t[r][1][tid] = __float2half(fmaf(0.2f, tanhf(a1), 1.0f));
        s_t[r][2][tid] = __float2half(fmaf(0.2f, tanhf(a2), 1.0f));
    }
    __syncthreads();

    const int w0 = tx * 8;
    const int hm = (h0 - 1) & (H - 1);
    const int hp = (h0 + 2) & (H - 1);
    const size_t base = (size_t)b * C * HW + (size_t)(2 * ty) * HW + w0;
    const float* pm = x + base + (size_t)hm * W;
    const float* p0 = x + base + (size_t)h0 * W;
    const float* pp = x + base + (size_t)hp * W;
    float*       o0 = out + base + (size_t)h0 * W;
    const size_t cstep = (size_t)16 * HW;   // 8 sub-lanes x 2 channels each

    const unsigned FULL = 0xffffffffu;
    const int laneL = (tx + 31) & 31;
    const int laneR = (tx + 1) & 31;
    const __half2 zero2 = __float2half2_rn(0.0f);
    const __half2 cap2  = __float2half2_rn(GAIN_CAP);

    // one output row for one channel. Steer mults arrive as 3 uint4 (already
    // loaded from shared; reused by both channels of the pair).
    auto do_row = [&](float4 cA_, float4 cB_, float4 sA_, float4 sB_,
                      const uint4& uH, const uint4& uV, const uint4& uD,
                      float invh, float invv, float invd,
                      __half2 gh2, __half2 gv2, __half2 gd2, float* op) {
        unsigned mh[4] = {uH.x, uH.y, uH.z, uH.w};
        unsigned mv[4] = {uV.x, uV.y, uV.z, uV.w};
        unsigned md[4] = {uD.x, uD.y, uD.z, uD.w};

        float ce[10], se[10];
        ce[1] = cA_.x; ce[2] = cA_.y; ce[3] = cA_.z; ce[4] = cA_.w;
        ce[5] = cB_.x; ce[6] = cB_.y; ce[7] = cB_.z; ce[8] = cB_.w;
        se[1] = sA_.x; se[2] = sA_.y; se[3] = sA_.z; se[4] = sA_.w;
        se[5] = sB_.x; se[6] = sB_.y; se[7] = sB_.z; se[8] = sB_.w;
        ce[0] = __shfl_sync(FULL, ce[8], laneL);
        ce[9] = __shfl_sync(FULL, ce[1], laneR);
        se[0] = __shfl_sync(FULL, se[8], laneL);
        se[9] = __shfl_sync(FULL, se[1], laneR);

        float r8[8];
        #pragma unroll
        for (int j = 0; j < 4; j++) {
            __half2 gH = __hmin2(__hmax2(__hmul2(gh2, u2h(mh[j])), zero2), cap2);
            __half2 gV = __hmin2(__hmax2(__hmul2(gv2, u2h(mv[j])), zero2), cap2);
            __half2 gD = __hmin2(__hmax2(__hmul2(gd2, u2h(md[j])), zero2), cap2);
            float2 ghf = __half22float2(gH);
            float2 gvf = __half22float2(gV);
            float2 gdf = __half22float2(gD);
            #pragma unroll
            for (int k = 0; k < 2; k++) {
                const int i = 2 * j + k;
                float cv = ce[i + 1];
                float fh = (ce[i] + ce[i + 2] - 2.0f * cv) * invh;
                float fv = (se[i + 1]          - 2.0f * cv) * invv;
                float fd = (se[i] + se[i + 2]  - 4.0f * cv) * invd;
                float gh = k ? ghf.y : ghf.x;
                float gv = k ? gvf.y : gvf.x;
                float gd = k ? gdf.y : gdf.x;
                r8[i] = fmaf(gh, fh, fmaf(gv, fv, fmaf(gd, fd, cv)));
            }
        }
        __stcs(reinterpret_cast<float4*>(op),
               make_float4(r8[0], r8[1], r8[2], r8[3]));
        __stcs(reinterpret_cast<float4*>(op + 4),
               make_float4(r8[4], r8[5], r8[6], r8[7]));
    };

    for (int c = 2 * ty; c < C; c += 16) {
        // front-batch ALL 16 row-vector loads (2 channels x rows m,a,b,p)
        float4 m0A = *reinterpret_cast<const float4*>(pm);
        float4 m0B = *reinterpret_cast<const float4*>(pm + 4);
        float4 a0A = *reinterpret_cast<const float4*>(p0);
        float4 a0B = *reinterpret_cast<const float4*>(p0 + 4);
        float4 b0A = *reinterpret_cast<const float4*>(p0 + W);
        float4 b0B = *reinterpret_cast<const float4*>(p0 + W + 4);
        float4 q0A = *reinterpret_cast<const float4*>(pp);
        float4 q0B = *reinterpret_cast<const float4*>(pp + 4);
        float4 m1A = *reinterpret_cast<const float4*>(pm + HW);
        float4 m1B = *reinterpret_cast<const float4*>(pm + HW + 4);
        float4 a1A = *reinterpret_cast<const float4*>(p0 + HW);
        float4 a1B = *reinterpret_cast<const float4*>(p0 + HW + 4);
        float4 b1A = *reinterpret_cast<const float4*>(p0 + HW + W);
        float4 b1B = *reinterpret_cast<const float4*>(p0 + HW + W + 4);
        float4 q1A = *reinterpret_cast<const float4*>(pp + HW);
        float4 q1B = *reinterpret_cast<const float4*>(pp + HW + 4);

        // per-channel constants (c and c+1)
        float invh0 = s_invh[c],     invv0 = s_invv[c],     invd0 = s_invd[c];
        float invh1 = s_invh[c + 1], invv1 = s_invv[c + 1], invd1 = s_invd[c + 1];
        __half2 gh20 = __float2half2_rn(s_gh[c]);
        __half2 gv20 = __float2half2_rn(s_gv[c]);
        __half2 gd20 = __float2half2_rn(s_gd[c]);
        __half2 gh21 = __float2half2_rn(s_gh[c + 1]);
        __half2 gv21 = __float2half2_rn(s_gv[c + 1]);
        __half2 gd21 = __float2half2_rn(s_gd[c + 1]);

        // ---- row h0 (mults shared by both channels) ----
        {
            uint4 uH = *reinterpret_cast<const uint4*>(&s_t[0][0][w0]);
            uint4 uV = *reinterpret_cast<const uint4*>(&s_t[0][1][w0]);
            uint4 uD = *reinterpret_cast<const uint4*>(&s_t[0][2][w0]);
            do_row(a0A, a0B, add4(m0A, b0A), add4(m0B, b0B), uH, uV, uD,
                   invh0, invv0, invd0, gh20, gv20, gd20, o0);
            do_row(a1A, a1B, add4(m1A, b1A), add4(m1B, b1B), uH, uV, uD,
                   invh1, invv1, invd1, gh21, gv21, gd21, o0 + HW);
        }
        // ---- row h1 ----
        {
            uint4 uH = *reinterpret_cast<const uint4*>(&s_t[1][0][w0]);
            uint4 uV = *reinterpret_cast<const uint4*>(&s_t[1][1][w0]);
            uint4 uD = *reinterpret_cast<const uint4*>(&s_t[1][2][w0]);
            do_row(b0A, b0B, add4(a0A, q0A), add4(a0B, q0B), uH, uV, uD,
                   invh0, invv0, invd0, gh20, gv20, gd20, o0 + W);
            do_row(b1A, b1B, add4(a1A, q1A), add4(a1B, q1B), uH, uV, uD,
                   invh1, invv1, invd1, gh21, gv21, gd21, o0 + HW + W);
        }

        pm += cstep; p0 += cstep; pp += cstep; o0 += cstep;
    }
}

extern "C" void kernel_launch(void* const* d_in, const int* in_sizes, int n_in,
                              void* d_out, int out_size)
{
    const float* x            = (const float*)d_in[0];
    const float* steer        = (const float*)d_in[1];
    const float* modulation   = (const float*)d_in[2];
    const float* r_center     = (const float*)d_in[3];
    const float* r_horizontal = (const float*)d_in[4];
    const float* r_vertical   = (const float*)d_in[5];
    const float* r_diag       = (const float*)d_in[6];
    const float* gain_h       = (const float*)d_in[7];
    const float* gain_v       = (const float*)d_in[8];
    const float* gain_d       = (const float*)d_in[9];
    const float* steer_w      = (const float*)d_in[10];
    const float* mod_w        = (const float*)d_in[11];
    float* out = (float*)d_out;

    dim3 block(32, 8, 1);       // warp = full W row; ty = channel-pair lane
    dim3 grid(H / 2, B, 1);     // one block per (row pair, b) = 512 blocks
    pwdm_kernel<<<grid, block>>>(x, steer, modulation,
                                 r_center, r_horizontal, r_vertical, r_diag,
                                 gain_h, gain_v, gain_d,
                                 steer_w, mod_w, out);
}